// round 12
// baseline (speedup 1.0000x reference)
#include <cuda_runtime.h>

#define B_TOT  8192
#define NN     82
#define HH     10
#define NOUT   5
#define TSTEPS 3
#define GB     7            // batches per block
#define BD     288          // 9 warps; active threads = 41*7 = 287 (2 nodes/thread)
#define NROW   12           // padded floats per (node,g) row -> 48B, 16B aligned
#define MHALF  41

// shared memory: adjacency + node states only
#define SM_ADJ   0                           // 2*NN*NN interleaved (in,out) pairs
#define SM_NODES (2*NN*NN)                   // NN*GB*NROW
#define SM_TOTAL (SM_NODES + NN*GB*NROW)

// dense weights + biases live in constant memory (broadcast-uniform reads)
__constant__ float c_w3w[200];
__constant__ float c_w4w[200];
__constant__ float c_w5w[200];
__constant__ float c_wout[100];
__constant__ float c_w3u[100];
__constant__ float c_w5u[100];
__constant__ float c_b3w[10];
__constant__ float c_b3u[10];
__constant__ float c_b4w[10];
__constant__ float c_b5w[10];
__constant__ float c_b5u[10];
__constant__ float c_bout[5];

union F4U { float4 v; unsigned long long u[2]; float f[4]; };
union F2U { unsigned long long u; float2 f; };

__device__ __forceinline__ unsigned long long pack2(float a, float b) {
    unsigned long long r;
    asm("mov.b64 %0, {%1, %2};" : "=l"(r) : "f"(a), "f"(b));
    return r;
}
__device__ __forceinline__ void fma2(unsigned long long& acc,
                                     unsigned long long a, unsigned long long b) {
    asm("fma.rn.f32x2 %0, %1, %2, %0;" : "+l"(acc) : "l"(a), "l"(b));
}
__device__ __forceinline__ float hsum2(unsigned long long p) {
    F2U u; u.u = p; return u.f.x + u.f.y;
}

__device__ __forceinline__ float sigmoid_f(float v) {
    return __fdividef(1.0f, 1.0f + __expf(-v));
}
__device__ __forceinline__ float tanh_f(float v) {
    return __fdividef(2.0f, 1.0f + __expf(-2.0f * v)) - 1.0f;
}

// load 10 floats from 16B-aligned SMEM as 5 f32x2 pairs
__device__ __forceinline__ void load10(const float* p, unsigned long long* d) {
    F4U q0, q1; F2U q2;
    q0.v = *(const float4*)(p);
    q1.v = *(const float4*)(p + 4);
    q2.f = *(const float2*)(p + 8);
    d[0] = q0.u[0]; d[1] = q0.u[1]; d[2] = q1.u[0]; d[3] = q1.u[1]; d[4] = q2.u;
}

// constant weight row (20 floats, 16B-aligned) dotted against TWO packed av sets
__device__ __forceinline__ void dot20x2c(const float* wrow,
                                         const unsigned long long* av0,
                                         const unsigned long long* av1,
                                         float& r0, float& r1) {
    unsigned long long a0 = 0ULL, a1 = 0ULL;
    #pragma unroll
    for (int q = 0; q < 5; q++) {
        F4U w_;
        w_.v = *(const float4*)(wrow + 4 * q);
        fma2(a0, w_.u[0], av0[2 * q]);
        fma2(a0, w_.u[1], av0[2 * q + 1]);
        fma2(a1, w_.u[0], av1[2 * q]);
        fma2(a1, w_.u[1], av1[2 * q + 1]);
    }
    r0 = hsum2(a0);
    r1 = hsum2(a1);
}

// constant u-row (10 floats, 8B-aligned) dotted against two packed vectors
__device__ __forceinline__ void dot10x2c(const float* urow,
                                         const unsigned long long* v0,
                                         const unsigned long long* v1,
                                         float& r0, float& r1) {
    unsigned long long a0 = 0ULL, a1 = 0ULL;
    #pragma unroll
    for (int p = 0; p < 5; p++) {
        F2U w; w.f = *(const float2*)(urow + 2 * p);
        fma2(a0, w.u, v0[p]);
        fma2(a1, w.u, v1[p]);
    }
    r0 = hsum2(a0);
    r1 = hsum2(a1);
}

// output head for one (node,batch)
__device__ __forceinline__ void out_head(const float* __restrict__ xr,
                                         const float* __restrict__ nr,
                                         float* __restrict__ op,
                                         float* __restrict__ fp)
{
    unsigned long long fnp[5], xp[5];
    load10(nr, fnp);
    #pragma unroll
    for (int p = 0; p < 5; p++) xp[p] = pack2(xr[2 * p], xr[2 * p + 1]);
    #pragma unroll
    for (int o = 0; o < NOUT; o++) {
        unsigned long long acc = 0ULL;
        #pragma unroll
        for (int q = 0; q < 5; q++) {
            F4U w_;
            w_.v = *(const float4*)(c_wout + o * 20 + 4 * q);
            unsigned long long opnd0 = (2 * q < 5)     ? fnp[2 * q]     : xp[2 * q - 5];
            unsigned long long opnd1 = (2 * q + 1 < 5) ? fnp[2 * q + 1] : xp[2 * q - 4];
            fma2(acc, w_.u[0], opnd0);
            fma2(acc, w_.u[1], opnd1);
        }
        op[o] = tanh_f(c_bout[o] + hsum2(acc));
    }
    #pragma unroll
    for (int h = 0; h < HH; h++) fp[h] = nr[h];
}

__global__ __launch_bounds__(BD, 2)
void ggnn_kernel(const float* __restrict__ x,
                 const float* __restrict__ in_adj,
                 const float* __restrict__ out_adj,
                 float* __restrict__ out0, float* __restrict__ outfn)
{
    extern __shared__ float sm[];
    const int tid = threadIdx.x;

    // ---- cooperative setup: adjacency interleave into smem (vectorized) ----
    for (int k = tid; k < (NN * NN) / 2; k += BD) {
        F2U a, b;
        a.f = *(const float2*)(in_adj  + 2 * k);
        b.f = *(const float2*)(out_adj + 2 * k);
        float4 w = make_float4(a.f.x, b.f.x, a.f.y, b.f.y);
        *(float4*)(sm + SM_ADJ + 4 * k) = w;
    }

    const int  i0  = tid / GB;       // node tile 0: 0..40
    const int  i1  = i0 + MHALF;     // node tile 1: 41..81
    const int  g   = tid - i0 * GB;  // batch-in-block
    const int  b   = blockIdx.x * GB + g;
    const bool act = (tid < MHALF * GB) && (b < B_TOT);

    float* nr0 = sm + SM_NODES + (i0 * GB + g) * NROW;
    float* nr1 = sm + SM_NODES + (i1 * GB + g) * NROW;

    if (act) {
        const float* xr0 = x + ((size_t)b * NN + i0) * HH;
        const float* xr1 = x + ((size_t)b * NN + i1) * HH;
        #pragma unroll
        for (int h = 0; h < HH; h++) { nr0[h] = xr0[h]; nr1[h] = xr1[h]; }
    }
    __syncthreads();

    for (int st = 0; st < TSTEPS; st++) {
        float fnn0[HH], fnn1[HH];
        if (act) {
            // ---- aggregation for both nodes; states loaded once ----
            unsigned long long av0[HH], av1[HH];  // [0..4]=a_in, [5..9]=a_out pairs
            #pragma unroll
            for (int p = 0; p < HH; p++) { av0[p] = 0ULL; av1[p] = 0ULL; }

            const float* arow0 = sm + SM_ADJ + i0 * (2 * NN);
            const float* arow1 = sm + SM_ADJ + i1 * (2 * NN);
            const float* nbase = sm + SM_NODES + g * NROW;
            for (int j = 0; j < NN; j += 2) {
                F4U a0; a0.v = *(const float4*)(arow0 + 2 * j);
                F4U a1; a1.v = *(const float4*)(arow1 + 2 * j);
                const float* xjs = nbase + j * (GB * NROW);
                unsigned long long s0[5], s1[5];
                load10(xjs, s0);
                load10(xjs + GB * NROW, s1);
                unsigned long long t;
                t = pack2(a0.f[0], a0.f[0]);
                #pragma unroll
                for (int p = 0; p < 5; p++) fma2(av0[p], t, s0[p]);
                t = pack2(a0.f[1], a0.f[1]);
                #pragma unroll
                for (int p = 0; p < 5; p++) fma2(av0[5 + p], t, s0[p]);
                t = pack2(a0.f[2], a0.f[2]);
                #pragma unroll
                for (int p = 0; p < 5; p++) fma2(av0[p], t, s1[p]);
                t = pack2(a0.f[3], a0.f[3]);
                #pragma unroll
                for (int p = 0; p < 5; p++) fma2(av0[5 + p], t, s1[p]);

                t = pack2(a1.f[0], a1.f[0]);
                #pragma unroll
                for (int p = 0; p < 5; p++) fma2(av1[p], t, s0[p]);
                t = pack2(a1.f[1], a1.f[1]);
                #pragma unroll
                for (int p = 0; p < 5; p++) fma2(av1[5 + p], t, s0[p]);
                t = pack2(a1.f[2], a1.f[2]);
                #pragma unroll
                for (int p = 0; p < 5; p++) fma2(av1[p], t, s1[p]);
                t = pack2(a1.f[3], a1.f[3]);
                #pragma unroll
                for (int p = 0; p < 5; p++) fma2(av1[5 + p], t, s1[p]);
            }

            // ---- pass 1: u3 = w3u . fn for both nodes ----
            float u30[HH], u31[HH];
            {
                unsigned long long f0[5], f1[5];
                load10(nr0, f0);
                load10(nr1, f1);
                #pragma unroll
                for (int h = 0; h < HH; h++)
                    dot10x2c(c_w3u + h * 10, f0, f1, u30[h], u31[h]);
            }

            // ---- pass 2: z gates ----
            float zv0[HH], zv1[HH];
            #pragma unroll
            for (int h = 0; h < HH; h++) {
                float d0, d1;
                dot20x2c(c_w3w + h * 20, av0, av1, d0, d1);
                float bz = c_b3w[h] + c_b3u[h];
                zv0[h] = sigmoid_f(bz + u30[h] + d0);
                zv1[h] = sigmoid_f(bz + u31[h] + d1);
            }

            // ---- pass 3: r gates folded with fn -> rf = r * fn ----
            unsigned long long rf0[5], rf1[5];
            #pragma unroll
            for (int p = 0; p < 5; p++) {
                float da0, da1, db0, db1;
                dot20x2c(c_w4w + (2 * p) * 20,     av0, av1, da0, da1);
                dot20x2c(c_w4w + (2 * p + 1) * 20, av0, av1, db0, db1);
                float bra = c_b4w[2 * p]     + c_b3u[2 * p];      // ref bug: r reuses b3u
                float brb = c_b4w[2 * p + 1] + c_b3u[2 * p + 1];
                float ra0 = sigmoid_f(bra + u30[2 * p]     + da0);
                float rb0 = sigmoid_f(brb + u30[2 * p + 1] + db0);
                float ra1 = sigmoid_f(bra + u31[2 * p]     + da1);
                float rb1 = sigmoid_f(brb + u31[2 * p + 1] + db1);
                rf0[p] = pack2(ra0 * nr0[2 * p], rb0 * nr0[2 * p + 1]);
                rf1[p] = pack2(ra1 * nr1[2 * p], rb1 * nr1[2 * p + 1]);
            }

            // ---- pass 4: candidate h + state update ----
            #pragma unroll
            for (int h = 0; h < HH; h++) {
                float w0, w1, v0, v1;
                dot20x2c(c_w5w + h * 20, av0, av1, w0, w1);
                dot10x2c(c_w5u + h * 10, rf0, rf1, v0, v1);
                float bh = c_b5w[h] + c_b5u[h];
                float h0 = tanh_f(bh + w0 + v0);
                float h1 = tanh_f(bh + w1 + v1);
                float o0 = nr0[h], o1 = nr1[h];
                fnn0[h] = o0 + zv0[h] * (h0 - o0);
                fnn1[h] = o1 + zv1[h] * (h1 - o1);
            }
        }
        __syncthreads();   // reads of old states done
        if (act) {
            #pragma unroll
            for (int h = 0; h < HH; h++) { nr0[h] = fnn0[h]; nr1[h] = fnn1[h]; }
        }
        __syncthreads();   // new states visible
    }

    // ---- output head for both nodes ----
    if (act) {
        const size_t row0 = (size_t)b * NN + i0;
        const size_t row1 = (size_t)b * NN + i1;
        out_head(x + row0 * HH, nr0, out0 + row0 * NOUT, outfn + row0 * HH);
        out_head(x + row1 * HH, nr1, out0 + row1 * NOUT, outfn + row1 * HH);
    }
}

extern "C" void kernel_launch(void* const* d_in, const int* in_sizes, int n_in,
                              void* d_out, int out_size)
{
    const float* x       = (const float*)d_in[0];
    const float* in_adj  = (const float*)d_in[1];
    const float* out_adj = (const float*)d_in[2];

    // stage dense weights/biases into constant memory (async D2D, capturable)
    cudaMemcpyToSymbolAsync(c_w3w,  d_in[3],  200 * 4, 0, cudaMemcpyDeviceToDevice, 0);
    cudaMemcpyToSymbolAsync(c_b3w,  d_in[4],   10 * 4, 0, cudaMemcpyDeviceToDevice, 0);
    cudaMemcpyToSymbolAsync(c_w3u,  d_in[5],  100 * 4, 0, cudaMemcpyDeviceToDevice, 0);
    cudaMemcpyToSymbolAsync(c_b3u,  d_in[6],   10 * 4, 0, cudaMemcpyDeviceToDevice, 0);
    cudaMemcpyToSymbolAsync(c_w4w,  d_in[7],  200 * 4, 0, cudaMemcpyDeviceToDevice, 0);
    cudaMemcpyToSymbolAsync(c_b4w,  d_in[8],   10 * 4, 0, cudaMemcpyDeviceToDevice, 0);
    cudaMemcpyToSymbolAsync(c_w5w,  d_in[9],  200 * 4, 0, cudaMemcpyDeviceToDevice, 0);
    cudaMemcpyToSymbolAsync(c_b5w,  d_in[10],  10 * 4, 0, cudaMemcpyDeviceToDevice, 0);
    cudaMemcpyToSymbolAsync(c_w5u,  d_in[11], 100 * 4, 0, cudaMemcpyDeviceToDevice, 0);
    cudaMemcpyToSymbolAsync(c_b5u,  d_in[12],  10 * 4, 0, cudaMemcpyDeviceToDevice, 0);
    cudaMemcpyToSymbolAsync(c_wout, d_in[13], 100 * 4, 0, cudaMemcpyDeviceToDevice, 0);
    cudaMemcpyToSymbolAsync(c_bout, d_in[14],   5 * 4, 0, cudaMemcpyDeviceToDevice, 0);

    float* out0  = (float*)d_out;
    float* outfn = out0 + (size_t)B_TOT * NN * NOUT;

    const size_t smbytes = SM_TOTAL * sizeof(float);
    cudaFuncSetAttribute(ggnn_kernel,
                         cudaFuncAttributeMaxDynamicSharedMemorySize,
                         (int)smbytes);

    const int grid = (B_TOT + GB - 1) / GB;
    ggnn_kernel<<<grid, BD, smbytes>>>(x, in_adj, out_adj, out0, outfn);
}

// round 13
// speedup vs baseline: 1.2180x; 1.2180x over previous
#include <cuda_runtime.h>

#define B_TOT  8192
#define NN     82
#define HH     10
#define NOUT   5
#define TSTEPS 3
#define GB     6            // batches per block
#define BD     256          // 8 warps; active threads = 41*6 = 246 (2 nodes/thread)
#define NROW   12           // padded floats per (node,g) row -> 48B, 16B aligned
#define MHALF  41
#define NODESZ (NN*GB*NROW) // one node-state buffer

// shared memory: adjacency + double-buffered node states
#define SM_ADJ   0                           // 2*NN*NN interleaved (in,out) pairs
#define SM_NODES (2*NN*NN)                   // buf0, then buf1
#define SM_TOTAL (SM_NODES + 2*NODESZ)

// dense weights + biases live in constant memory (broadcast-uniform reads)
__constant__ float c_w3w[200];
__constant__ float c_w4w[200];
__constant__ float c_w5w[200];
__constant__ float c_wout[100];
__constant__ float c_w3u[100];
__constant__ float c_w5u[100];
__constant__ float c_b3w[10];
__constant__ float c_b3u[10];
__constant__ float c_b4w[10];
__constant__ float c_b5w[10];
__constant__ float c_b5u[10];
__constant__ float c_bout[5];

union F4U { float4 v; unsigned long long u[2]; float f[4]; };
union F2U { unsigned long long u; float2 f; };

__device__ __forceinline__ unsigned long long pack2(float a, float b) {
    unsigned long long r;
    asm("mov.b64 %0, {%1, %2};" : "=l"(r) : "f"(a), "f"(b));
    return r;
}
__device__ __forceinline__ void fma2(unsigned long long& acc,
                                     unsigned long long a, unsigned long long b) {
    asm("fma.rn.f32x2 %0, %1, %2, %0;" : "+l"(acc) : "l"(a), "l"(b));
}
__device__ __forceinline__ float hsum2(unsigned long long p) {
    F2U u; u.u = p; return u.f.x + u.f.y;
}

__device__ __forceinline__ float sigmoid_f(float v) {
    return __fdividef(1.0f, 1.0f + __expf(-v));
}
__device__ __forceinline__ float tanh_f(float v) {
    return __fdividef(2.0f, 1.0f + __expf(-2.0f * v)) - 1.0f;
}

// load 10 floats from 16B-aligned SMEM as 5 f32x2 pairs
__device__ __forceinline__ void load10(const float* p, unsigned long long* d) {
    F4U q0, q1; F2U q2;
    q0.v = *(const float4*)(p);
    q1.v = *(const float4*)(p + 4);
    q2.f = *(const float2*)(p + 8);
    d[0] = q0.u[0]; d[1] = q0.u[1]; d[2] = q1.u[0]; d[3] = q1.u[1]; d[4] = q2.u;
}

// constant weight row (20 floats, 16B-aligned) dotted against TWO packed av sets
__device__ __forceinline__ void dot20x2c(const float* wrow,
                                         const unsigned long long* av0,
                                         const unsigned long long* av1,
                                         float& r0, float& r1) {
    unsigned long long a0 = 0ULL, a1 = 0ULL;
    #pragma unroll
    for (int q = 0; q < 5; q++) {
        F4U w_;
        w_.v = *(const float4*)(wrow + 4 * q);
        fma2(a0, w_.u[0], av0[2 * q]);
        fma2(a0, w_.u[1], av0[2 * q + 1]);
        fma2(a1, w_.u[0], av1[2 * q]);
        fma2(a1, w_.u[1], av1[2 * q + 1]);
    }
    r0 = hsum2(a0);
    r1 = hsum2(a1);
}

// constant u-row (10 floats, 8B-aligned) dotted against two packed vectors
__device__ __forceinline__ void dot10x2c(const float* urow,
                                         const unsigned long long* v0,
                                         const unsigned long long* v1,
                                         float& r0, float& r1) {
    unsigned long long a0 = 0ULL, a1 = 0ULL;
    #pragma unroll
    for (int p = 0; p < 5; p++) {
        F2U w; w.f = *(const float2*)(urow + 2 * p);
        fma2(a0, w.u, v0[p]);
        fma2(a1, w.u, v1[p]);
    }
    r0 = hsum2(a0);
    r1 = hsum2(a1);
}

// output head for one (node,batch)
__device__ __forceinline__ void out_head(const float* __restrict__ xr,
                                         const float* __restrict__ nr,
                                         float* __restrict__ op,
                                         float* __restrict__ fp)
{
    unsigned long long fnp[5], xp[5];
    load10(nr, fnp);
    #pragma unroll
    for (int p = 0; p < 5; p++) xp[p] = pack2(xr[2 * p], xr[2 * p + 1]);
    #pragma unroll
    for (int o = 0; o < NOUT; o++) {
        unsigned long long acc = 0ULL;
        #pragma unroll
        for (int q = 0; q < 5; q++) {
            F4U w_;
            w_.v = *(const float4*)(c_wout + o * 20 + 4 * q);
            unsigned long long opnd0 = (2 * q < 5)     ? fnp[2 * q]     : xp[2 * q - 5];
            unsigned long long opnd1 = (2 * q + 1 < 5) ? fnp[2 * q + 1] : xp[2 * q - 4];
            fma2(acc, w_.u[0], opnd0);
            fma2(acc, w_.u[1], opnd1);
        }
        op[o] = tanh_f(c_bout[o] + hsum2(acc));
    }
    #pragma unroll
    for (int h = 0; h < HH; h++) fp[h] = nr[h];
}

__global__ __launch_bounds__(BD, 2)
void ggnn_kernel(const float* __restrict__ x,
                 const float* __restrict__ in_adj,
                 const float* __restrict__ out_adj,
                 float* __restrict__ out0, float* __restrict__ outfn)
{
    extern __shared__ float sm[];
    const int tid = threadIdx.x;

    // ---- cooperative setup: adjacency interleave into smem (vectorized) ----
    for (int k = tid; k < (NN * NN) / 2; k += BD) {
        F2U a, b;
        a.f = *(const float2*)(in_adj  + 2 * k);
        b.f = *(const float2*)(out_adj + 2 * k);
        float4 w = make_float4(a.f.x, b.f.x, a.f.y, b.f.y);
        *(float4*)(sm + SM_ADJ + 4 * k) = w;
    }

    const int  i0  = tid / GB;       // node tile 0: 0..40
    const int  i1  = i0 + MHALF;     // node tile 1: 41..81
    const int  g   = tid - i0 * GB;  // batch-in-block
    const int  b   = blockIdx.x * GB + g;
    const bool act = (tid < MHALF * GB) && (b < B_TOT);

    const int off0 = (i0 * GB + g) * NROW;   // row offsets within a buffer
    const int off1 = (i1 * GB + g) * NROW;

    if (act) {
        const float* xr0 = x + ((size_t)b * NN + i0) * HH;
        const float* xr1 = x + ((size_t)b * NN + i1) * HH;
        float* w0 = sm + SM_NODES + off0;
        float* w1 = sm + SM_NODES + off1;
        #pragma unroll
        for (int h = 0; h < HH; h++) { w0[h] = xr0[h]; w1[h] = xr1[h]; }
    }
    __syncthreads();

    int rd = 0;   // buffer being read this step
    for (int st = 0; st < TSTEPS; st++) {
        const float* rbase = sm + SM_NODES + rd * NODESZ;
        float*       wbase = sm + SM_NODES + (1 - rd) * NODESZ;
        const float* nr0 = rbase + off0;
        const float* nr1 = rbase + off1;

        if (act) {
            // ---- aggregation for both nodes; states loaded once ----
            unsigned long long av0[HH], av1[HH];  // [0..4]=a_in, [5..9]=a_out pairs
            #pragma unroll
            for (int p = 0; p < HH; p++) { av0[p] = 0ULL; av1[p] = 0ULL; }

            const float* arow0 = sm + SM_ADJ + i0 * (2 * NN);
            const float* arow1 = sm + SM_ADJ + i1 * (2 * NN);
            const float* nbase = rbase + g * NROW;
            for (int j = 0; j < NN; j += 2) {
                F4U a0; a0.v = *(const float4*)(arow0 + 2 * j);
                F4U a1; a1.v = *(const float4*)(arow1 + 2 * j);
                const float* xjs = nbase + j * (GB * NROW);
                unsigned long long s0[5], s1[5];
                load10(xjs, s0);
                load10(xjs + GB * NROW, s1);
                unsigned long long t;
                t = pack2(a0.f[0], a0.f[0]);
                #pragma unroll
                for (int p = 0; p < 5; p++) fma2(av0[p], t, s0[p]);
                t = pack2(a0.f[1], a0.f[1]);
                #pragma unroll
                for (int p = 0; p < 5; p++) fma2(av0[5 + p], t, s0[p]);
                t = pack2(a0.f[2], a0.f[2]);
                #pragma unroll
                for (int p = 0; p < 5; p++) fma2(av0[p], t, s1[p]);
                t = pack2(a0.f[3], a0.f[3]);
                #pragma unroll
                for (int p = 0; p < 5; p++) fma2(av0[5 + p], t, s1[p]);

                t = pack2(a1.f[0], a1.f[0]);
                #pragma unroll
                for (int p = 0; p < 5; p++) fma2(av1[p], t, s0[p]);
                t = pack2(a1.f[1], a1.f[1]);
                #pragma unroll
                for (int p = 0; p < 5; p++) fma2(av1[5 + p], t, s0[p]);
                t = pack2(a1.f[2], a1.f[2]);
                #pragma unroll
                for (int p = 0; p < 5; p++) fma2(av1[p], t, s1[p]);
                t = pack2(a1.f[3], a1.f[3]);
                #pragma unroll
                for (int p = 0; p < 5; p++) fma2(av1[5 + p], t, s1[p]);
            }

            // ---- pass 1: u3 = w3u . fn for both nodes ----
            float u30[HH], u31[HH];
            {
                unsigned long long f0[5], f1[5];
                load10(nr0, f0);
                load10(nr1, f1);
                #pragma unroll
                for (int h = 0; h < HH; h++)
                    dot10x2c(c_w3u + h * 10, f0, f1, u30[h], u31[h]);
            }

            // ---- pass 2: z gates ----
            float zv0[HH], zv1[HH];
            #pragma unroll
            for (int h = 0; h < HH; h++) {
                float d0, d1;
                dot20x2c(c_w3w + h * 20, av0, av1, d0, d1);
                float bz = c_b3w[h] + c_b3u[h];
                zv0[h] = sigmoid_f(bz + u30[h] + d0);
                zv1[h] = sigmoid_f(bz + u31[h] + d1);
            }

            // ---- pass 3: r gates folded with fn -> rf = r * fn ----
            unsigned long long rf0[5], rf1[5];
            #pragma unroll
            for (int p = 0; p < 5; p++) {
                float da0, da1, db0, db1;
                dot20x2c(c_w4w + (2 * p) * 20,     av0, av1, da0, da1);
                dot20x2c(c_w4w + (2 * p + 1) * 20, av0, av1, db0, db1);
                float bra = c_b4w[2 * p]     + c_b3u[2 * p];      // ref bug: r reuses b3u
                float brb = c_b4w[2 * p + 1] + c_b3u[2 * p + 1];
                float ra0 = sigmoid_f(bra + u30[2 * p]     + da0);
                float rb0 = sigmoid_f(brb + u30[2 * p + 1] + db0);
                float ra1 = sigmoid_f(bra + u31[2 * p]     + da1);
                float rb1 = sigmoid_f(brb + u31[2 * p + 1] + db1);
                rf0[p] = pack2(ra0 * nr0[2 * p], rb0 * nr0[2 * p + 1]);
                rf1[p] = pack2(ra1 * nr1[2 * p], rb1 * nr1[2 * p + 1]);
            }

            // ---- pass 4: candidate h + state update -> write OTHER buffer ----
            float* wr0 = wbase + off0;
            float* wr1 = wbase + off1;
            #pragma unroll
            for (int h = 0; h < HH; h++) {
                float w0, w1, v0, v1;
                dot20x2c(c_w5w + h * 20, av0, av1, w0, w1);
                dot10x2c(c_w5u + h * 10, rf0, rf1, v0, v1);
                float bh = c_b5w[h] + c_b5u[h];
                float h0 = tanh_f(bh + w0 + v0);
                float h1 = tanh_f(bh + w1 + v1);
                float o0 = nr0[h], o1 = nr1[h];
                wr0[h] = o0 + zv0[h] * (h0 - o0);
                wr1[h] = o1 + zv1[h] * (h1 - o1);
            }
        }
        __syncthreads();   // single barrier: new buffer visible to all
        rd = 1 - rd;
    }

    // ---- output head for both nodes (final state in buffer `rd`) ----
    if (act) {
        const float* rbase = sm + SM_NODES + rd * NODESZ;
        const size_t row0 = (size_t)b * NN + i0;
        const size_t row1 = (size_t)b * NN + i1;
        out_head(x + row0 * HH, rbase + off0, out0 + row0 * NOUT, outfn + row0 * HH);
        out_head(x + row1 * HH, rbase + off1, out0 + row1 * NOUT, outfn + row1 * HH);
    }
}

extern "C" void kernel_launch(void* const* d_in, const int* in_sizes, int n_in,
                              void* d_out, int out_size)
{
    const float* x       = (const float*)d_in[0];
    const float* in_adj  = (const float*)d_in[1];
    const float* out_adj = (const float*)d_in[2];

    // stage dense weights/biases into constant memory (async D2D, capturable)
    cudaMemcpyToSymbolAsync(c_w3w,  d_in[3],  200 * 4, 0, cudaMemcpyDeviceToDevice, 0);
    cudaMemcpyToSymbolAsync(c_b3w,  d_in[4],   10 * 4, 0, cudaMemcpyDeviceToDevice, 0);
    cudaMemcpyToSymbolAsync(c_w3u,  d_in[5],  100 * 4, 0, cudaMemcpyDeviceToDevice, 0);
    cudaMemcpyToSymbolAsync(c_b3u,  d_in[6],   10 * 4, 0, cudaMemcpyDeviceToDevice, 0);
    cudaMemcpyToSymbolAsync(c_w4w,  d_in[7],  200 * 4, 0, cudaMemcpyDeviceToDevice, 0);
    cudaMemcpyToSymbolAsync(c_b4w,  d_in[8],   10 * 4, 0, cudaMemcpyDeviceToDevice, 0);
    cudaMemcpyToSymbolAsync(c_w5w,  d_in[9],  200 * 4, 0, cudaMemcpyDeviceToDevice, 0);
    cudaMemcpyToSymbolAsync(c_b5w,  d_in[10],  10 * 4, 0, cudaMemcpyDeviceToDevice, 0);
    cudaMemcpyToSymbolAsync(c_w5u,  d_in[11], 100 * 4, 0, cudaMemcpyDeviceToDevice, 0);
    cudaMemcpyToSymbolAsync(c_b5u,  d_in[12],  10 * 4, 0, cudaMemcpyDeviceToDevice, 0);
    cudaMemcpyToSymbolAsync(c_wout, d_in[13], 100 * 4, 0, cudaMemcpyDeviceToDevice, 0);
    cudaMemcpyToSymbolAsync(c_bout, d_in[14],   5 * 4, 0, cudaMemcpyDeviceToDevice, 0);

    float* out0  = (float*)d_out;
    float* outfn = out0 + (size_t)B_TOT * NN * NOUT;

    const size_t smbytes = SM_TOTAL * sizeof(float);
    cudaFuncSetAttribute(ggnn_kernel,
                         cudaFuncAttributeMaxDynamicSharedMemorySize,
                         (int)smbytes);

    const int grid = (B_TOT + GB - 1) / GB;
    ggnn_kernel<<<grid, BD, smbytes>>>(x, in_adj, out_adj, out0, outfn);
}

// round 14
// speedup vs baseline: 1.2305x; 1.0103x over previous
#include <cuda_runtime.h>

#define B_TOT  8192
#define NN     82
#define HH     10
#define NOUT   5
#define TSTEPS 3
#define GB     6            // batches per block
#define BD     256          // 8 warps; active threads = 41*6 = 246 (2 nodes/thread)
#define NROW   12           // padded floats per (node,g) row -> 48B, 16B aligned
#define MHALF  41

// shared memory: adjacency + node states only
#define SM_ADJ   0                           // 2*NN*NN interleaved (in,out) pairs
#define SM_NODES (2*NN*NN)                   // NN*GB*NROW
#define SM_TOTAL (SM_NODES + NN*GB*NROW)

// dense weights + biases live in constant memory (broadcast-uniform reads)
__constant__ float c_w3w[200];
__constant__ float c_w4w[200];
__constant__ float c_w5w[200];
__constant__ float c_wout[100];
__constant__ float c_w3u[100];
__constant__ float c_w5u[100];
__constant__ float c_b3w[10];
__constant__ float c_b3u[10];
__constant__ float c_b4w[10];
__constant__ float c_b5w[10];
__constant__ float c_b5u[10];
__constant__ float c_bout[5];

union F4U { float4 v; unsigned long long u[2]; float f[4]; };
union F2U { unsigned long long u; float2 f; };

__device__ __forceinline__ unsigned long long pack2(float a, float b) {
    unsigned long long r;
    asm("mov.b64 %0, {%1, %2};" : "=l"(r) : "f"(a), "f"(b));
    return r;
}
__device__ __forceinline__ void fma2(unsigned long long& acc,
                                     unsigned long long a, unsigned long long b) {
    asm("fma.rn.f32x2 %0, %1, %2, %0;" : "+l"(acc) : "l"(a), "l"(b));
}
__device__ __forceinline__ float hsum2(unsigned long long p) {
    F2U u; u.u = p; return u.f.x + u.f.y;
}

__device__ __forceinline__ float sigmoid_f(float v) {
    return __fdividef(1.0f, 1.0f + __expf(-v));
}
__device__ __forceinline__ float tanh_f(float v) {
    return __fdividef(2.0f, 1.0f + __expf(-2.0f * v)) - 1.0f;
}

// load 10 floats from 16B-aligned SMEM as 5 f32x2 pairs
__device__ __forceinline__ void load10(const float* p, unsigned long long* d) {
    F4U q0, q1; F2U q2;
    q0.v = *(const float4*)(p);
    q1.v = *(const float4*)(p + 4);
    q2.f = *(const float2*)(p + 8);
    d[0] = q0.u[0]; d[1] = q0.u[1]; d[2] = q1.u[0]; d[3] = q1.u[1]; d[4] = q2.u;
}

// constant weight row (20 floats, 16B-aligned) dotted against TWO packed av sets
__device__ __forceinline__ void dot20x2c(const float* wrow,
                                         const unsigned long long* av0,
                                         const unsigned long long* av1,
                                         float& r0, float& r1) {
    unsigned long long a0 = 0ULL, a1 = 0ULL;
    #pragma unroll
    for (int q = 0; q < 5; q++) {
        F4U w_;
        w_.v = *(const float4*)(wrow + 4 * q);
        fma2(a0, w_.u[0], av0[2 * q]);
        fma2(a0, w_.u[1], av0[2 * q + 1]);
        fma2(a1, w_.u[0], av1[2 * q]);
        fma2(a1, w_.u[1], av1[2 * q + 1]);
    }
    r0 = hsum2(a0);
    r1 = hsum2(a1);
}

// constant u-row (10 floats, 8B-aligned) dotted against two packed vectors
__device__ __forceinline__ void dot10x2c(const float* urow,
                                         const unsigned long long* v0,
                                         const unsigned long long* v1,
                                         float& r0, float& r1) {
    unsigned long long a0 = 0ULL, a1 = 0ULL;
    #pragma unroll
    for (int p = 0; p < 5; p++) {
        F2U w; w.f = *(const float2*)(urow + 2 * p);
        fma2(a0, w.u, v0[p]);
        fma2(a1, w.u, v1[p]);
    }
    r0 = hsum2(a0);
    r1 = hsum2(a1);
}

// inner aggregation body for one j-pair (states s0,s1 shared by both nodes)
__device__ __forceinline__ void agg_pair(const F4U& a0, const F4U& a1,
                                         const unsigned long long* s0,
                                         const unsigned long long* s1,
                                         unsigned long long* av0,
                                         unsigned long long* av1) {
    unsigned long long t;
    t = pack2(a0.f[0], a0.f[0]);
    #pragma unroll
    for (int p = 0; p < 5; p++) fma2(av0[p], t, s0[p]);
    t = pack2(a0.f[1], a0.f[1]);
    #pragma unroll
    for (int p = 0; p < 5; p++) fma2(av0[5 + p], t, s0[p]);
    t = pack2(a0.f[2], a0.f[2]);
    #pragma unroll
    for (int p = 0; p < 5; p++) fma2(av0[p], t, s1[p]);
    t = pack2(a0.f[3], a0.f[3]);
    #pragma unroll
    for (int p = 0; p < 5; p++) fma2(av0[5 + p], t, s1[p]);

    t = pack2(a1.f[0], a1.f[0]);
    #pragma unroll
    for (int p = 0; p < 5; p++) fma2(av1[p], t, s0[p]);
    t = pack2(a1.f[1], a1.f[1]);
    #pragma unroll
    for (int p = 0; p < 5; p++) fma2(av1[5 + p], t, s0[p]);
    t = pack2(a1.f[2], a1.f[2]);
    #pragma unroll
    for (int p = 0; p < 5; p++) fma2(av1[p], t, s1[p]);
    t = pack2(a1.f[3], a1.f[3]);
    #pragma unroll
    for (int p = 0; p < 5; p++) fma2(av1[5 + p], t, s1[p]);
}

// output head for one (node,batch)
__device__ __forceinline__ void out_head(const float* __restrict__ xr,
                                         const float* __restrict__ nr,
                                         float* __restrict__ op,
                                         float* __restrict__ fp)
{
    unsigned long long fnp[5], xp[5];
    load10(nr, fnp);
    #pragma unroll
    for (int p = 0; p < 5; p++) xp[p] = pack2(xr[2 * p], xr[2 * p + 1]);
    #pragma unroll
    for (int o = 0; o < NOUT; o++) {
        unsigned long long acc = 0ULL;
        #pragma unroll
        for (int q = 0; q < 5; q++) {
            F4U w_;
            w_.v = *(const float4*)(c_wout + o * 20 + 4 * q);
            unsigned long long opnd0 = (2 * q < 5)     ? fnp[2 * q]     : xp[2 * q - 5];
            unsigned long long opnd1 = (2 * q + 1 < 5) ? fnp[2 * q + 1] : xp[2 * q - 4];
            fma2(acc, w_.u[0], opnd0);
            fma2(acc, w_.u[1], opnd1);
        }
        op[o] = tanh_f(c_bout[o] + hsum2(acc));
    }
    #pragma unroll
    for (int h = 0; h < HH; h++) fp[h] = nr[h];
}

__global__ __launch_bounds__(BD, 2)
void ggnn_kernel(const float* __restrict__ x,
                 const float* __restrict__ in_adj,
                 const float* __restrict__ out_adj,
                 float* __restrict__ out0, float* __restrict__ outfn)
{
    extern __shared__ float sm[];
    const int tid = threadIdx.x;

    // ---- cooperative setup: adjacency interleave into smem (vectorized) ----
    for (int k = tid; k < (NN * NN) / 2; k += BD) {
        F2U a, b;
        a.f = *(const float2*)(in_adj  + 2 * k);
        b.f = *(const float2*)(out_adj + 2 * k);
        float4 w = make_float4(a.f.x, b.f.x, a.f.y, b.f.y);
        *(float4*)(sm + SM_ADJ + 4 * k) = w;
    }

    const int  i0  = tid / GB;       // node tile 0: 0..40
    const int  i1  = i0 + MHALF;     // node tile 1: 41..81
    const int  g   = tid - i0 * GB;  // batch-in-block
    const int  b   = blockIdx.x * GB + g;
    const bool act = (tid < MHALF * GB) && (b < B_TOT);

    float* nr0 = sm + SM_NODES + (i0 * GB + g) * NROW;
    float* nr1 = sm + SM_NODES + (i1 * GB + g) * NROW;

    if (act) {
        const float* xr0 = x + ((size_t)b * NN + i0) * HH;
        const float* xr1 = x + ((size_t)b * NN + i1) * HH;
        #pragma unroll
        for (int h = 0; h < HH; h++) { nr0[h] = xr0[h]; nr1[h] = xr1[h]; }
    }
    __syncthreads();

    for (int st = 0; st < TSTEPS; st++) {
        float fnn0[HH], fnn1[HH];
        if (act) {
            // ---- aggregation for both nodes; states loaded once ----
            unsigned long long av0[HH], av1[HH];  // [0..4]=a_in, [5..9]=a_out pairs
            #pragma unroll
            for (int p = 0; p < HH; p++) { av0[p] = 0ULL; av1[p] = 0ULL; }

            const float* arow0 = sm + SM_ADJ + i0 * (2 * NN);
            const float* arow1 = sm + SM_ADJ + i1 * (2 * NN);
            const float* nbase = sm + SM_NODES + g * NROW;
            #pragma unroll 2
            for (int j = 0; j < NN; j += 2) {
                F4U a0; a0.v = *(const float4*)(arow0 + 2 * j);
                F4U a1; a1.v = *(const float4*)(arow1 + 2 * j);
                const float* xjs = nbase + j * (GB * NROW);
                unsigned long long s0[5], s1[5];
                load10(xjs, s0);
                load10(xjs + GB * NROW, s1);
                agg_pair(a0, a1, s0, s1, av0, av1);
            }

            // ---- pass 1: u3 = w3u . fn for both nodes ----
            float u30[HH], u31[HH];
            {
                unsigned long long f0[5], f1[5];
                load10(nr0, f0);
                load10(nr1, f1);
                #pragma unroll
                for (int h = 0; h < HH; h++)
                    dot10x2c(c_w3u + h * 10, f0, f1, u30[h], u31[h]);
            }

            // ---- pass 2: z gates ----
            float zv0[HH], zv1[HH];
            #pragma unroll
            for (int h = 0; h < HH; h++) {
                float d0, d1;
                dot20x2c(c_w3w + h * 20, av0, av1, d0, d1);
                float bz = c_b3w[h] + c_b3u[h];
                zv0[h] = sigmoid_f(bz + u30[h] + d0);
                zv1[h] = sigmoid_f(bz + u31[h] + d1);
            }

            // ---- pass 3: r gates folded with fn -> rf = r * fn ----
            unsigned long long rf0[5], rf1[5];
            #pragma unroll
            for (int p = 0; p < 5; p++) {
                float da0, da1, db0, db1;
                dot20x2c(c_w4w + (2 * p) * 20,     av0, av1, da0, da1);
                dot20x2c(c_w4w + (2 * p + 1) * 20, av0, av1, db0, db1);
                float bra = c_b4w[2 * p]     + c_b3u[2 * p];      // ref bug: r reuses b3u
                float brb = c_b4w[2 * p + 1] + c_b3u[2 * p + 1];
                float ra0 = sigmoid_f(bra + u30[2 * p]     + da0);
                float rb0 = sigmoid_f(brb + u30[2 * p + 1] + db0);
                float ra1 = sigmoid_f(bra + u31[2 * p]     + da1);
                float rb1 = sigmoid_f(brb + u31[2 * p + 1] + db1);
                rf0[p] = pack2(ra0 * nr0[2 * p], rb0 * nr0[2 * p + 1]);
                rf1[p] = pack2(ra1 * nr1[2 * p], rb1 * nr1[2 * p + 1]);
            }

            // ---- pass 4: candidate h + state update ----
            #pragma unroll
            for (int h = 0; h < HH; h++) {
                float w0, w1, v0, v1;
                dot20x2c(c_w5w + h * 20, av0, av1, w0, w1);
                dot10x2c(c_w5u + h * 10, rf0, rf1, v0, v1);
                float bh = c_b5w[h] + c_b5u[h];
                float h0 = tanh_f(bh + w0 + v0);
                float h1 = tanh_f(bh + w1 + v1);
                float o0 = nr0[h], o1 = nr1[h];
                fnn0[h] = o0 + zv0[h] * (h0 - o0);
                fnn1[h] = o1 + zv1[h] * (h1 - o1);
            }
        }
        __syncthreads();   // reads of old states done
        if (act) {
            #pragma unroll
            for (int h = 0; h < HH; h++) { nr0[h] = fnn0[h]; nr1[h] = fnn1[h]; }
        }
        __syncthreads();   // new states visible
    }

    // ---- output head for both nodes ----
    if (act) {
        const size_t row0 = (size_t)b * NN + i0;
        const size_t row1 = (size_t)b * NN + i1;
        out_head(x + row0 * HH, nr0, out0 + row0 * NOUT, outfn + row0 * HH);
        out_head(x + row1 * HH, nr1, out0 + row1 * NOUT, outfn + row1 * HH);
    }
}

extern "C" void kernel_launch(void* const* d_in, const int* in_sizes, int n_in,
                              void* d_out, int out_size)
{
    const float* x       = (const float*)d_in[0];
    const float* in_adj  = (const float*)d_in[1];
    const float* out_adj = (const float*)d_in[2];

    // stage dense weights/biases into constant memory (async D2D, capturable)
    cudaMemcpyToSymbolAsync(c_w3w,  d_in[3],  200 * 4, 0, cudaMemcpyDeviceToDevice, 0);
    cudaMemcpyToSymbolAsync(c_b3w,  d_in[4],   10 * 4, 0, cudaMemcpyDeviceToDevice, 0);
    cudaMemcpyToSymbolAsync(c_w3u,  d_in[5],  100 * 4, 0, cudaMemcpyDeviceToDevice, 0);
    cudaMemcpyToSymbolAsync(c_b3u,  d_in[6],   10 * 4, 0, cudaMemcpyDeviceToDevice, 0);
    cudaMemcpyToSymbolAsync(c_w4w,  d_in[7],  200 * 4, 0, cudaMemcpyDeviceToDevice, 0);
    cudaMemcpyToSymbolAsync(c_b4w,  d_in[8],   10 * 4, 0, cudaMemcpyDeviceToDevice, 0);
    cudaMemcpyToSymbolAsync(c_w5w,  d_in[9],  200 * 4, 0, cudaMemcpyDeviceToDevice, 0);
    cudaMemcpyToSymbolAsync(c_b5w,  d_in[10],  10 * 4, 0, cudaMemcpyDeviceToDevice, 0);
    cudaMemcpyToSymbolAsync(c_w5u,  d_in[11], 100 * 4, 0, cudaMemcpyDeviceToDevice, 0);
    cudaMemcpyToSymbolAsync(c_b5u,  d_in[12],  10 * 4, 0, cudaMemcpyDeviceToDevice, 0);
    cudaMemcpyToSymbolAsync(c_wout, d_in[13], 100 * 4, 0, cudaMemcpyDeviceToDevice, 0);
    cudaMemcpyToSymbolAsync(c_bout, d_in[14],   5 * 4, 0, cudaMemcpyDeviceToDevice, 0);

    float* out0  = (float*)d_out;
    float* outfn = out0 + (size_t)B_TOT * NN * NOUT;

    const size_t smbytes = SM_TOTAL * sizeof(float);
    cudaFuncSetAttribute(ggnn_kernel,
                         cudaFuncAttributeMaxDynamicSharedMemorySize,
                         (int)smbytes);

    const int grid = (B_TOT + GB - 1) / GB;
    ggnn_kernel<<<grid, BD, smbytes>>>(x, in_adj, out_adj, out0, outfn);
}